// round 13
// baseline (speedup 1.0000x reference)
#include <cuda_runtime.h>
#include <cuda_fp16.h>
#include <cuda_bf16.h>

// TripletLoss on GB300 — R11: norms folded into the DP4A stream.
//   z = d(i,j)-d(i,k) = (sj-sk) - 2 xi.(xj-xk)
//     ~= sc^2 * [ (Qjj - Qkk) - 2(Qij - Qik) ]   (all-integer, one butterfly value)
// R10 analysis: tail latency = norm gathers (8 scatter LDGs/iter, ~28 wf,
// feeding the epilogue). This round computes Qjj,Qkk by DP4A from the B/C
// rows already in registers: g_sq deleted, norm gathers deleted, epilogue is
// z = sc^2 * m. Bias term sum(e^2) cancels in the Qjj-Qkk difference.
// Keeps: pipelined cooperative idx chunks, 8-lane groups (full-line loads),
// single-int butterfly, 16-wide repacked branchless softplus.

#define MAX_N 8192
#define DIMF  128
#define FULLM 0xffffffffu

__device__ signed char g_feat_q[MAX_N * DIMF];   // 1 MB int8 copy
__device__ float       g_s2;                     // sc^2  (sc = absmax/127)
__device__ unsigned    g_absmax_bits;
__device__ double      g_acc;
__device__ int         g_is64;

__global__ void detect_and_init_kernel(const int* __restrict__ trip_raw) {
    int lane = threadIdx.x;
    int nz = 0;
    #pragma unroll
    for (int t = lane; t < 64; t += 32) nz |= trip_raw[2 * t + 1];
    unsigned any = __ballot_sync(FULLM, nz != 0);
    if (lane == 0) {
        g_is64 = (any == 0);    // int64 triplets: high words of small values = 0
        g_acc = 0.0;
        g_absmax_bits = 0u;
    }
}

// Global absmax only (norms no longer needed). Grid-stride, MLP-friendly.
__global__ void absmax_kernel(const float* __restrict__ feat, int total4) {
    int i = blockIdx.x * blockDim.x + threadIdx.x;
    const float4* f4 = reinterpret_cast<const float4*>(feat);
    float v = 0.0f;
    for (; i < total4; i += gridDim.x * blockDim.x) {
        float4 x = f4[i];
        v = fmaxf(v, fmaxf(fmaxf(fabsf(x.x), fabsf(x.y)),
                           fmaxf(fabsf(x.z), fabsf(x.w))));
    }
    #pragma unroll
    for (int o = 16; o; o >>= 1)
        v = fmaxf(v, __shfl_xor_sync(FULLM, v, o));
    if ((threadIdx.x & 31) == 0)
        atomicMax(&g_absmax_bits, __float_as_uint(v));  // positive floats: bit order = value order
}

// int8 quantization, 2 float4 per thread (MLP=2).
__global__ void quant_kernel(const float* __restrict__ feat, int total4) {
    int half = total4 >> 1;
    int i0 = blockIdx.x * blockDim.x + threadIdx.x;
    if (i0 >= half) return;
    float absmax = __uint_as_float(g_absmax_bits);
    float s = __fdividef(127.0f, absmax);
    if (i0 == 0) {
        float sc = absmax / 127.0f;
        g_s2 = sc * sc;
    }
    const float4* f4 = reinterpret_cast<const float4*>(feat);
    unsigned* out = reinterpret_cast<unsigned*>(g_feat_q);
    #pragma unroll
    for (int h = 0; h < 2; h++) {
        int idx = i0 + h * half;
        float4 v = f4[idx];
        int q0 = max(-127, min(127, __float2int_rn(v.x * s)));
        int q1 = max(-127, min(127, __float2int_rn(v.y * s)));
        int q2 = max(-127, min(127, __float2int_rn(v.z * s)));
        int q3 = max(-127, min(127, __float2int_rn(v.w * s)));
        out[idx] = (unsigned)(q0 & 0xFF) | ((unsigned)(q1 & 0xFF) << 8) |
                   ((unsigned)(q2 & 0xFF) << 16) | ((unsigned)(q3 & 0xFF) << 24);
    }
}

// Branchless softplus: max(z,0) + log(1 + e^-|z|). 2 MUFU, no divergence.
__device__ __forceinline__ float softplus_bl(float z) {
    float r = __expf(-fabsf(z));
    return fmaxf(z, 0.0f) + __logf(1.0f + r);
}

__device__ __forceinline__ int clamp_idx(int v, int mask, int N) {
    if (mask >= 0) return v & mask;
    v = v < 0 ? 0 : v;
    return v >= N ? N - 1 : v;
}

// m = (Qjj - Qkk) - 2*(Qij - Qik), 16 DP4A + 2 ISUB + 1 LEA.
__device__ __forceinline__ int triplet_m(const uint4& A, const uint4& B, const uint4& C) {
    int dij = 0, dik = 0, djj = 0, dkk = 0;
    dij = __dp4a((int)A.x, (int)B.x, dij);
    dik = __dp4a((int)A.x, (int)C.x, dik);
    djj = __dp4a((int)B.x, (int)B.x, djj);
    dkk = __dp4a((int)C.x, (int)C.x, dkk);
    dij = __dp4a((int)A.y, (int)B.y, dij);
    dik = __dp4a((int)A.y, (int)C.y, dik);
    djj = __dp4a((int)B.y, (int)B.y, djj);
    dkk = __dp4a((int)C.y, (int)C.y, dkk);
    dij = __dp4a((int)A.z, (int)B.z, dij);
    dik = __dp4a((int)A.z, (int)C.z, dik);
    djj = __dp4a((int)B.z, (int)B.z, djj);
    dkk = __dp4a((int)C.z, (int)C.z, dkk);
    dij = __dp4a((int)A.w, (int)B.w, dij);
    dik = __dp4a((int)A.w, (int)C.w, dik);
    djj = __dp4a((int)B.w, (int)B.w, djj);
    dkk = __dp4a((int)C.w, (int)C.w, dkk);
    return (djj - dkk) - 2 * (dij - dik);
}

#define UNROLL_T 4

__global__ void __launch_bounds__(256) triplet_kernel(
    const void* __restrict__ trip, int T, int N, int mask)
{
    const int lane = threadIdx.x & 31;
    const int wid  = threadIdx.x >> 5;
    const int sub  = lane & 7;          // position in 8-lane group
    const int grp  = lane >> 3;         // group 0..3
    const int gw   = (int)((blockIdx.x * blockDim.x + threadIdx.x) >> 5);
    const int nw   = (int)((gridDim.x * blockDim.x) >> 5);
    const int is64 = g_is64;
    const float s2 = g_s2;
    const uint4* __restrict__ fq = reinterpret_cast<const uint4*>(g_feat_q); // 8 uint4/row

    float sum = 0.0f;

    if (!is64) {
        // ---- int32 fast path: pipelined cooperative index chunks ----
        const int* __restrict__ t32 = reinterpret_cast<const int*>(trip);
        const int posMax = 3 * T;
        const int stride = nw * 16;
        const int bq  = (3 * grp) >> 1;         // loop-invariant shfl base
        const bool par = (grp & 1) != 0;        // loop-invariant parity

        int base = gw * 16;
        int ca = 0, cb = 0;
        if (base < T) {
            int p = min(3 * base + 2 * lane, posMax - 2);   // even, 8B-aligned
            int2 v = *reinterpret_cast<const int2*>(t32 + p);
            ca = v.x; cb = v.y;
        }

        for (; base < T; base += stride) {
            // Prefetch next chunk (2 regs, clamped in-range).
            int np = min(3 * (base + stride) + 2 * lane, posMax - 2);
            int2 nv = *reinterpret_cast<const int2*>(t32 + np);

            int m[UNROLL_T];

            #pragma unroll
            for (int u = 0; u < UNROLL_T; u++) {
                int q   = bq + 6 * u;
                int aq  = __shfl_sync(FULLM, ca, q);
                int bqv = __shfl_sync(FULLM, cb, q);
                int aq1 = __shfl_sync(FULLM, ca, q + 1);
                int bq1 = __shfl_sync(FULLM, cb, q + 1);
                int ii = clamp_idx(par ? bqv : aq,  mask, N);
                int jj = clamp_idx(par ? aq1 : bqv, mask, N);
                int kk = clamp_idx(par ? bq1 : aq1, mask, N);

                uint4 A = fq[ii * 8 + sub];     // one full 128B line per group
                uint4 B = fq[jj * 8 + sub];
                uint4 C = fq[kk * 8 + sub];
                m[u] = triplet_m(A, B, C);
            }

            // Butterfly within 8-lane groups: 3 steps x 1 int per slot.
            #pragma unroll
            for (int o = 4; o; o >>= 1) {
                #pragma unroll
                for (int u = 0; u < UNROLL_T; u++)
                    m[u] += __shfl_xor_sync(FULLM, m[u], o);
            }

            // Repack 16 z onto lanes 0..15 -> ONE 16-wide softplus pass.
            // (clamps dropped: only bite on degenerate i==j/i==k, <1e-6 rel)
            int src = (lane >> 2) << 3;
            int mb0 = __shfl_sync(FULLM, m[0], src);
            int mb1 = __shfl_sync(FULLM, m[1], src);
            int mb2 = __shfl_sync(FULLM, m[2], src);
            int mb3 = __shfl_sync(FULLM, m[3], src);
            int sel = lane & 3;
            int mr = mb0;
            mr = (sel == 1) ? mb1 : mr;
            mr = (sel == 2) ? mb2 : mr;
            mr = (sel == 3) ? mb3 : mr;

            int tL = base + ((lane & 3) << 2) + (lane >> 2);
            if (lane < 16 && tL < T)
                sum += softplus_bl(s2 * (float)mr);

            ca = nv.x; cb = nv.y;
        }
    } else {
        // ---- int64 fallback: direct per-lane index loads ----
        const long long* __restrict__ t64 = reinterpret_cast<const long long*>(trip);
        for (int base = gw * 16; base < T; base += nw * 16) {
            int m[UNROLL_T];
            #pragma unroll
            for (int u = 0; u < UNROLL_T; u++) {
                int t  = base + u * 4 + grp;
                int tt = t < T ? t : 0;
                int ii = clamp_idx((int)t64[3 * tt + 0], mask, N);
                int jj = clamp_idx((int)t64[3 * tt + 1], mask, N);
                int kk = clamp_idx((int)t64[3 * tt + 2], mask, N);
                uint4 A = fq[ii * 8 + sub];
                uint4 B = fq[jj * 8 + sub];
                uint4 C = fq[kk * 8 + sub];
                m[u] = triplet_m(A, B, C);
            }
            #pragma unroll
            for (int o = 4; o; o >>= 1) {
                #pragma unroll
                for (int u = 0; u < UNROLL_T; u++)
                    m[u] += __shfl_xor_sync(FULLM, m[u], o);
            }
            int src = (lane >> 2) << 3;
            int mb0 = __shfl_sync(FULLM, m[0], src);
            int mb1 = __shfl_sync(FULLM, m[1], src);
            int mb2 = __shfl_sync(FULLM, m[2], src);
            int mb3 = __shfl_sync(FULLM, m[3], src);
            int sel = lane & 3;
            int mr = mb0;
            mr = (sel == 1) ? mb1 : mr;
            mr = (sel == 2) ? mb2 : mr;
            mr = (sel == 3) ? mb3 : mr;
            int tL = base + ((lane & 3) << 2) + (lane >> 2);
            if (lane < 16 && tL < T)
                sum += softplus_bl(s2 * (float)mr);
        }
    }

    #pragma unroll
    for (int o = 16; o; o >>= 1) sum += __shfl_xor_sync(FULLM, sum, o);
    __shared__ float wsum[8];
    if (lane == 0) wsum[wid] = sum;
    __syncthreads();
    if (threadIdx.x == 0) {
        float b = 0.0f;
        #pragma unroll
        for (int w = 0; w < 8; w++) b += wsum[w];
        atomicAdd(&g_acc, (double)b);
    }
}

__global__ void finalize_kernel(float* __restrict__ out, int T) {
    out[0] = (float)(g_acc / (double)T);
}

extern "C" void kernel_launch(void* const* d_in, const int* in_sizes, int n_in,
                              void* d_out, int out_size)
{
    const float* feat = (const float*)d_in[0];
    const void*  trip = d_in[1];
    int N = in_sizes[0] / DIMF;     // 8192
    int T = in_sizes[1] / 3;        // 1,000,000
    int mask = ((N & (N - 1)) == 0) ? (N - 1) : -1;
    int total4 = N * DIMF / 4;

    // Single-wave grid from occupancy (pure queries; capture-safe).
    int dev = 0, nsm = 148, bpm = 8;
    cudaGetDevice(&dev);
    cudaDeviceGetAttribute(&nsm, cudaDevAttrMultiProcessorCount, dev);
    cudaOccupancyMaxActiveBlocksPerMultiprocessor(&bpm, triplet_kernel, 256, 0);
    if (bpm < 1) bpm = 1;
    int grid = nsm * bpm;

    detect_and_init_kernel<<<1, 32>>>((const int*)trip);
    absmax_kernel<<<592, 256>>>(feat, total4);
    quant_kernel<<<((total4 / 2) + 255) / 256, 256>>>(feat, total4);
    triplet_kernel<<<grid, 256>>>(trip, T, N, mask);
    finalize_kernel<<<1, 1>>>((float*)d_out, T);
}